// round 10
// baseline (speedup 1.0000x reference)
#include <cuda_runtime.h>
#include <cuda_bf16.h>
#include <math.h>
#include <stdint.h>
#include <stddef.h>

#define B_ 128
#define H_ 8
#define DK 64
#define C_ 50000
#define D_ 512
#define TILE_C 64
#define NTILE 782          // 782*64 = 50048 >= 50000
#define NTILE_PAD 800      // padded; tiles 782..799 never written (stay zero)
#define NCHUNK 32
#define CHTILES 25         // 32*25 = 800 == NTILE_PAD

#define COS_M 0.9800665778412416f
#define SIN_M 0.19866933079506122f
#define TH_  (-0.9800665778412416f)
#define MM_  0.039733866159012244f
#define S_   30.0f
#define QS   31500.0f
// exp(q*30/31500 - 30) == exp2(q*QINV2 - S2_)
#define QINV2 1.3739952770371081e-3f
#define S2_   43.280851226668902f

// ---- pass1 smem layout (bytes) ----
#define OFF_AH 0
#define OFF_AL 16384
#define OFF_BH 32768
#define OFF_BL 40960
#define OFF_WINV 49152     // 64 floats
#define OFF_WP   49408     // 256 floats
#define OFF_PS   50432     // 256 floats
#define SMEM1    51456

// ---- k_out smem ----
#define KO_INV 0
#define KO_STG 4096
#define SMEM2 (4096 + 128 * 68 * 4)   // 38912 dynamic (+1KB static red[])

// ---------------- device scratch ----------------
__device__ __align__(16) __nv_bfloat16 g_Asw[H_ * 16384];   // per head: [hi][lo], swizzled
__device__ uint32_t g_Q[(size_t)H_ * NTILE * 8 * 512];      // packed int16 q-pairs (102MB)
__device__ float g_psum[H_ * NTILE_PAD * B_];               // zero-padded tiles
__device__ __align__(16) float g_psum2[B_ * H_ * NCHUNK];   // transposed: [(b*8+h)][chunk]
__device__ float g_invsum[B_ * H_];
__device__ float g_coslab[B_ * H_];
__device__ int   g_label[B_];
__device__ unsigned int g_ctr = 0;                          // self-resetting ticket

// ---------------- helpers ----------------
__device__ __forceinline__ uint32_t smem_u32(const void* p) {
    uint32_t a;
    asm("{ .reg .u64 t; cvta.to.shared.u64 t, %1; cvt.u32.u64 %0, t; }" : "=r"(a) : "l"(p));
    return a;
}
__device__ __forceinline__ unsigned swz(unsigned by) { return by ^ ((by >> 3) & 0x70); }
__device__ __forceinline__ float ex2a(float x) {
    float y;
    asm("ex2.approx.f32 %0, %1;" : "=f"(y) : "f"(x));
    return y;
}
__device__ __forceinline__ void ldsm4(uint32_t* r, uint32_t addr) {
    asm volatile("ldmatrix.sync.aligned.m8n8.x4.shared.b16 {%0,%1,%2,%3}, [%4];"
                 : "=r"(r[0]), "=r"(r[1]), "=r"(r[2]), "=r"(r[3]) : "r"(addr));
}
__device__ __forceinline__ void mma_bf16(float* d, const uint32_t* a, uint32_t b0, uint32_t b1) {
    asm volatile("mma.sync.aligned.m16n8k16.row.col.f32.bf16.bf16.f32 "
                 "{%0,%1,%2,%3}, {%4,%5,%6,%7}, {%8,%9}, {%0,%1,%2,%3};"
                 : "+f"(d[0]), "+f"(d[1]), "+f"(d[2]), "+f"(d[3])
                 : "r"(a[0]), "r"(a[1]), "r"(a[2]), "r"(a[3]), "r"(b0), "r"(b1));
}
// pack two floats to bf16x2 (rn); low = a, high = b
__device__ __forceinline__ uint32_t cvt_bf16x2(float a, float b) {
    uint32_t r;
    asm("cvt.rn.bf16x2.f32 %0, %1, %2;" : "=r"(r) : "f"(b), "f"(a));
    return r;
}

// ---------------- xnorm (+ label decode in block 0, branchless detect) -----
__global__ void k_xnorm(const float* __restrict__ x, const int* __restrict__ raw) {
    __shared__ float wpz[16];
    __shared__ int is64;
    int b = blockIdx.x, t = threadIdx.x;
    if (b == 0 && t == 0) {
        int acc = 0;
        #pragma unroll
        for (int i = 0; i < 64; i++) acc |= raw[2 * i + 1];
        is64 = (acc == 0);
    }
    float v = x[b * D_ + t];
    float s = v * v;
    #pragma unroll
    for (int o = 16; o > 0; o >>= 1) s += __shfl_down_sync(0xffffffffu, s, o);
    if ((t & 31) == 0) wpz[t >> 5] = s;
    __syncthreads();
    if (b == 0 && t < 128) g_label[t] = is64 ? raw[2 * t] : raw[t];
    int h = t >> 6, k = t & 63;
    float ss = wpz[2 * h] + wpz[2 * h + 1];
    float xn = v * (1.0f / fmaxf(sqrtf(ss), 1e-12f));
    __nv_bfloat16 hi = __float2bfloat16(xn);
    __nv_bfloat16 lo = __float2bfloat16(xn - __bfloat162float(hi));
    unsigned by = (unsigned)b * 128u + 2u * (unsigned)k;
    unsigned sw = swz(by);
    g_Asw[h * 16384 + (sw >> 1)] = hi;
    g_Asw[h * 16384 + 8192 + (sw >> 1)] = lo;
}

// ---------------- pass1: GEMM + margin + quantize + partial sums ----------------
// Half-split mainloop: acc[16] per 16-col half -> fits 64 regs -> 4 CTAs/SM.
__global__ __launch_bounds__(256, 4) void k_pass1(const float* __restrict__ w) {
    extern __shared__ char sm[];
    const int tid = threadIdx.x, warp = tid >> 5, lane = tid & 31;
    const int h = blockIdx.y, tile = blockIdx.x, c0 = tile * TILE_C;
    uint32_t sb = smem_u32(sm);

    // copy A limbs (32KB, pre-swizzled; L2-resident)
    {
        const uint4* src = (const uint4*)(g_Asw + h * 16384);
        uint4* dst = (uint4*)(sm + OFF_AH);
        #pragma unroll
        for (int i = 0; i < 8; i++) dst[tid + 256 * i] = src[tid + 256 * i];
    }
    // convert B tile (64 cols) to bf16 limbs via packed cvt (+ per-col sqnorm)
    {
        int c = tid & 63, kg = tid >> 6;
        int cg = c0 + c;
        bool valid = cg < C_;
        const float* wp0 = w + ((size_t)(h * DK + kg * 16)) * C_ + cg;
        float ss = 0.f;
        #pragma unroll
        for (int i = 0; i < 8; i++) {
            float v0 = valid ? __ldg(wp0 + (size_t)(2 * i) * C_) : 0.f;
            float v1 = valid ? __ldg(wp0 + (size_t)(2 * i + 1) * C_) : 0.f;
            ss = fmaf(v0, v0, ss); ss = fmaf(v1, v1, ss);
            uint32_t hpk = cvt_bf16x2(v0, v1);
            float r0 = v0 - __uint_as_float(hpk << 16);
            float r1 = v1 - __uint_as_float(hpk & 0xFFFF0000u);
            uint32_t lpk = cvt_bf16x2(r0, r1);
            unsigned by = (unsigned)c * 128u + (unsigned)(kg * 32 + 4 * i);
            unsigned sw = swz(by);
            *(uint32_t*)(sm + OFF_BH + sw) = hpk;
            *(uint32_t*)(sm + OFF_BL + sw) = lpk;
        }
        ((float*)(sm + OFF_WP))[c * 4 + kg] = ss;
    }
    __syncthreads();
    if (tid < 64) {
        float* wp = (float*)(sm + OFF_WP);
        ((float*)(sm + OFF_WINV))[tid] =
            1.0f / fmaxf(sqrtf(wp[tid * 4] + wp[tid * 4 + 1] + wp[tid * 4 + 2] + wp[tid * 4 + 3]),
                         1e-12f);
    }
    __syncthreads();

    const int wm = warp >> 1, wn = warp & 1;
    const int m0 = wm * 32, n0 = wn * 32;
    const int lrow = lane & 7, lt = lane >> 3;
    const int rowAo = lrow + (lt & 1) * 8;
    const int kbAo = (lt >> 1) * 16;
    const int rowBo = lrow + (lt >> 1) * 8;
    const int kbBo = (lt & 1) * 16;

    const float* winv = (const float*)(sm + OFF_WINV);
    float* ps = (float*)(sm + OFF_PS);
    const int r0 = m0 + (lane >> 2);
    int labr[4];
    #pragma unroll
    for (int i = 0; i < 4; i++) labr[i] = g_label[r0 + (i >> 1) * 16 + (i & 1) * 8];

    float rsum[4] = {0.f, 0.f, 0.f, 0.f};
    const size_t wbase = (((size_t)h * NTILE + tile) * 8 + warp) * 512;

    #pragma unroll 1
    for (int p = 0; p < 2; p++) {
        float acc[16];
        #pragma unroll
        for (int i = 0; i < 16; i++) acc[i] = 0.f;

        #pragma unroll
        for (int ks = 0; ks < 4; ks++) {
            uint32_t aH[2][4], aL[2][4];
            #pragma unroll
            for (int mb = 0; mb < 2; mb++) {
                unsigned swA = swz((unsigned)((m0 + mb * 16 + rowAo) * 128 + ks * 32 + kbAo));
                ldsm4(aH[mb], sb + OFF_AH + swA);
                ldsm4(aL[mb], sb + OFF_AL + swA);
            }
            unsigned swB = swz((unsigned)((n0 + p * 16 + rowBo) * 128 + ks * 32 + kbBo));
            uint32_t bH[4], bL[4];
            ldsm4(bH, sb + OFF_BH + swB);
            ldsm4(bL, sb + OFF_BL + swB);
            #pragma unroll
            for (int mb = 0; mb < 2; mb++) {
                float* d0 = acc + (mb * 2 + 0) * 4;
                float* d1 = acc + (mb * 2 + 1) * 4;
                mma_bf16(d0, aH[mb], bH[0], bH[1]);
                mma_bf16(d1, aH[mb], bH[2], bH[3]);
                mma_bf16(d0, aH[mb], bL[0], bL[1]);
                mma_bf16(d1, aH[mb], bL[2], bL[3]);
                mma_bf16(d0, aL[mb], bH[0], bH[1]);
                mma_bf16(d1, aL[mb], bH[2], bH[3]);
            }
        }

        // epilogue for this 16-col half: cosine -> margin -> quantize -> exp2
        #pragma unroll
        for (int mb = 0; mb < 2; mb++) {
            #pragma unroll
            for (int pnl = 0; pnl < 2; pnl++) {
                int pn = p * 2 + pnl;
                int cb = n0 + pn * 8 + (lane & 3) * 2;
                float w0 = winv[cb], w1 = winv[cb + 1];
                int cg = c0 + cb;
                uint2 pk2;
                #pragma unroll
                for (int pr = 0; pr < 2; pr++) {
                    int row = r0 + mb * 16 + pr * 8;
                    int lb = labr[mb * 2 + pr];
                    float v0 = acc[(mb * 2 + pnl) * 4 + pr * 2 + 0];
                    float v1 = acc[(mb * 2 + pnl) * 4 + pr * 2 + 1];
                    float cos0 = v0 * w0, cos1 = v1 * w1;
                    int qi0 = 0, qi1 = 0;
                    if (cg < C_) {
                        float val = cos0;
                        if (cg == lb) {
                            float sn = sqrtf(fmaxf(1.f - cos0 * cos0, 0.f));
                            float ph = cos0 * COS_M - sn * SIN_M;
                            val = (cos0 > TH_) ? ph : (cos0 - MM_);
                            g_coslab[row * H_ + h] = cos0;
                        }
                        qi0 = __float2int_rn(val * QS);
                        rsum[mb * 2 + pr] += ex2a(fmaf((float)qi0, QINV2, -S2_));
                    }
                    if (cg + 1 < C_) {
                        float val = cos1;
                        if (cg + 1 == lb) {
                            float sn = sqrtf(fmaxf(1.f - cos1 * cos1, 0.f));
                            float ph = cos1 * COS_M - sn * SIN_M;
                            val = (cos1 > TH_) ? ph : (cos1 - MM_);
                            g_coslab[row * H_ + h] = cos1;
                        }
                        qi1 = __float2int_rn(val * QS);
                        rsum[mb * 2 + pr] += ex2a(fmaf((float)qi1, QINV2, -S2_));
                    }
                    uint32_t pk = ((uint32_t)(uint16_t)(short)qi0) |
                                  (((uint32_t)(uint16_t)(short)qi1) << 16);
                    if (pr == 0) pk2.x = pk; else pk2.y = pk;
                }
                *(uint2*)&g_Q[wbase + (size_t)(mb * 4 + pn) * 64 + lane * 2] = pk2;
            }
        }
    }

    #pragma unroll
    for (int i = 0; i < 4; i++) {
        float v = rsum[i];
        v += __shfl_down_sync(0xffffffffu, v, 1);
        v += __shfl_down_sync(0xffffffffu, v, 2);
        if ((lane & 3) == 0)
            ps[(r0 + (i >> 1) * 16 + (i & 1) * 8) * 2 + wn] = v;
    }
    __syncthreads();
    if (tid < 128)
        g_psum[((size_t)h * NTILE_PAD + tile) * B_ + tid] = ps[tid * 2] + ps[tid * 2 + 1];
}

// ---------------- fused reduction: stage-1 + last-block invsum --------------
__global__ void k_sumred() {
    __shared__ unsigned int ticket;
    int h = blockIdx.x, ch = blockIdx.y, b = threadIdx.x;
    int t0 = ch * CHTILES;
    float s = 0.f;
    #pragma unroll
    for (int t = 0; t < CHTILES; t++)
        s += g_psum[((size_t)h * NTILE_PAD + t0 + t) * B_ + b];
    g_psum2[(b * H_ + h) * NCHUNK + ch] = s;
    __threadfence();
    __syncthreads();
    if (threadIdx.x == 0) ticket = atomicAdd(&g_ctr, 1u);
    __syncthreads();
    if (ticket == H_ * NCHUNK - 1) {
        __threadfence();
        #pragma unroll
        for (int i = 0; i < 8; i++) {
            int idx = threadIdx.x + 128 * i;     // b*8+h
            const float4* p = (const float4*)&g_psum2[idx * NCHUNK];
            float ss = 0.f;
            #pragma unroll
            for (int cc = 0; cc < NCHUNK / 4; cc++) {
                float4 v = p[cc];
                ss += (v.x + v.y) + (v.z + v.w);
            }
            g_invsum[idx] = 1.0f / ss;
        }
        if (threadIdx.x == 0) g_ctr = 0;         // reset for next graph replay
    }
}

// ---------------- k_out: head-mean of softmax (+ loss in block 0) -----------
__global__ __launch_bounds__(256, 4) void k_out(float* __restrict__ out, int write_loss) {
    extern __shared__ char sm[];
    __shared__ float red[256];
    const int tid = threadIdx.x, warp = tid >> 5, lane = tid & 31;
    const int tile = blockIdx.x, c0 = tile * TILE_C;
    float* invs = (float*)(sm + KO_INV);
    float* stg = (float*)(sm + KO_STG);
    #pragma unroll
    for (int i = 0; i < 4; i++) invs[tid + 256 * i] = g_invsum[tid + 256 * i] * 0.125f;

    // block 0 additionally computes the NLL loss (concurrent with other blocks)
    if (blockIdx.x == 0) {
        float nll = 0.f;
        #pragma unroll
        for (int i = 0; i < 4; i++) {
            int idx = tid + 256 * i;              // b*8+h
            float iv = g_invsum[idx];
            float cos = g_coslab[idx];
            float sn = sqrtf(fmaxf(1.0f - cos * cos, 0.0f));
            float ph = cos * COS_M - sn * SIN_M;
            float val = (cos > TH_) ? ph : (cos - MM_);
            nll += -(S_ * val - S_ + logf(iv));
        }
        red[tid] = nll;
        __syncthreads();
        #pragma unroll
        for (int st = 128; st > 0; st >>= 1) {
            if (tid < st) red[tid] += red[tid + st];
            __syncthreads();
        }
        if (tid == 0 && write_loss)
            out[(size_t)B_ * C_] = red[0] * (1.0f / (B_ * H_));
    }
    __syncthreads();

    const int wm = warp >> 1, wn = warp & 1;
    const int m0 = wm * 32, n0 = wn * 32;
    const int r0 = m0 + (lane >> 2);

    float acc[32];
    #pragma unroll
    for (int i = 0; i < 32; i++) acc[i] = 0.f;

    for (int h = 0; h < H_; h++) {
        const uint32_t* Qp = g_Q + (((size_t)h * NTILE + tile) * 8 + warp) * 512;
        float s[4];
        #pragma unroll
        for (int i = 0; i < 4; i++)
            s[i] = invs[(r0 + (i >> 1) * 16 + (i & 1) * 8) * H_ + h];
        #pragma unroll
        for (int mb = 0; mb < 2; mb++)
            #pragma unroll
            for (int pn = 0; pn < 4; pn++) {
                uint2 pk2 = *(const uint2*)&Qp[(size_t)(mb * 4 + pn) * 64 + lane * 2];
                #pragma unroll
                for (int pr = 0; pr < 2; pr++) {
                    uint32_t pk = pr ? pk2.y : pk2.x;
                    float q0 = (float)(short)(pk & 0xFFFFu);
                    float q1 = (float)(short)(pk >> 16);
                    float sv = s[mb * 2 + pr];
                    float e0 = ex2a(fmaf(q0, QINV2, -S2_));
                    float e1 = ex2a(fmaf(q1, QINV2, -S2_));
                    int ai = (mb * 4 + pn) * 4 + pr * 2;
                    acc[ai]     = fmaf(e0, sv, acc[ai]);
                    acc[ai + 1] = fmaf(e1, sv, acc[ai + 1]);
                }
            }
    }
    #pragma unroll
    for (int mb = 0; mb < 2; mb++)
        #pragma unroll
        for (int pn = 0; pn < 4; pn++)
            #pragma unroll
            for (int pr = 0; pr < 2; pr++) {
                int row = r0 + mb * 16 + pr * 8;
                int col = n0 + pn * 8 + (lane & 3) * 2;
                int ai = (mb * 4 + pn) * 4 + pr * 2;
                stg[row * 68 + col] = acc[ai];
                stg[row * 68 + col + 1] = acc[ai + 1];
            }
    __syncthreads();
    for (int idx = tid; idx < 2048; idx += 256) {
        int b = idx >> 4, c4 = (idx & 15) << 2;
        int cg = c0 + c4;
        if (cg + 3 < C_) {
            float4 vv = make_float4(stg[b * 68 + c4], stg[b * 68 + c4 + 1],
                                    stg[b * 68 + c4 + 2], stg[b * 68 + c4 + 3]);
            *(float4*)&out[(size_t)b * C_ + cg] = vv;
        } else {
            #pragma unroll
            for (int j = 0; j < 4; j++)
                if (cg + j < C_) out[(size_t)b * C_ + cg + j] = stg[b * 68 + c4 + j];
        }
    }
}

// ---------------- launcher ----------------
extern "C" void kernel_launch(void* const* d_in, const int* in_sizes, int n_in,
                              void* d_out, int out_size) {
    const float* x = (const float*)d_in[0];
    const float* w = (const float*)d_in[1];
    const int*   lab = (const int*)d_in[2];
    float* out = (float*)d_out;
    (void)in_sizes; (void)n_in;

    static int inited = 0;
    if (!inited) {
        cudaFuncSetAttribute(k_pass1, cudaFuncAttributeMaxDynamicSharedMemorySize, SMEM1);
        cudaFuncSetAttribute(k_out, cudaFuncAttributeMaxDynamicSharedMemorySize, SMEM2);
        inited = 1;
    }
    int write_loss = (out_size > B_ * C_) ? 1 : 0;

    k_xnorm<<<B_, D_>>>(x, lab);
    {
        dim3 g1(NTILE, H_);
        k_pass1<<<g1, 256, SMEM1>>>(w);
    }
    {
        dim3 g2(H_, NCHUNK);
        k_sumred<<<g2, B_>>>();
    }
    k_out<<<NTILE, 256, SMEM2>>>(out, write_loss);
}

// round 11
// speedup vs baseline: 1.0877x; 1.0877x over previous
#include <cuda_runtime.h>
#include <cuda_bf16.h>
#include <math.h>
#include <stdint.h>
#include <stddef.h>

#define B_ 128
#define H_ 8
#define DK 64
#define C_ 50000
#define D_ 512
#define TILE_C 64
#define NTILE 782          // 782*64 = 50048 >= 50000
#define NTILE_PAD 800      // padded; tiles 782..799 never written (stay zero)
#define NCHUNK 32
#define CHTILES 25         // 32*25 = 800 == NTILE_PAD

#define COS_M 0.9800665778412416f
#define SIN_M 0.19866933079506122f
#define TH_  (-0.9800665778412416f)
#define MM_  0.039733866159012244f
#define S_   30.0f
#define QS   31500.0f
// exp(q*30/31500 - 30) == exp2(q*QINV2 - S2_)
#define QINV2 1.3739952770371081e-3f
#define S2_   43.280851226668902f

// ---- pass1 smem layout (bytes) ----
#define OFF_AH 0
#define OFF_AL 16384
#define OFF_BH 32768
#define OFF_BL 40960
#define OFF_WINV 49152     // 64 floats
#define OFF_WP   49408     // 256 floats
#define OFF_PS   50432     // 256 floats
#define SMEM1    51456

// ---------------- device scratch ----------------
__device__ __align__(16) __nv_bfloat16 g_Asw[H_ * 16384];   // per head: [hi][lo], swizzled
__device__ uint32_t g_Q[(size_t)H_ * NTILE * 8 * 512];      // packed int16 q-pairs (102MB)
__device__ float g_psum[H_ * NTILE_PAD * B_];               // zero-padded tiles
__device__ __align__(16) float g_psum2[B_ * H_ * NCHUNK];   // transposed: [(b*8+h)][chunk]
__device__ float g_invsum[B_ * H_];
__device__ float g_coslab[B_ * H_];
__device__ int   g_label[B_];
__device__ unsigned int g_ctr = 0;                          // self-resetting ticket

// ---------------- helpers ----------------
__device__ __forceinline__ uint32_t smem_u32(const void* p) {
    uint32_t a;
    asm("{ .reg .u64 t; cvta.to.shared.u64 t, %1; cvt.u32.u64 %0, t; }" : "=r"(a) : "l"(p));
    return a;
}
__device__ __forceinline__ unsigned swz(unsigned by) { return by ^ ((by >> 3) & 0x70); }
__device__ __forceinline__ float ex2a(float x) {
    float y;
    asm("ex2.approx.f32 %0, %1;" : "=f"(y) : "f"(x));
    return y;
}
__device__ __forceinline__ void ldsm4(uint32_t* r, uint32_t addr) {
    asm volatile("ldmatrix.sync.aligned.m8n8.x4.shared.b16 {%0,%1,%2,%3}, [%4];"
                 : "=r"(r[0]), "=r"(r[1]), "=r"(r[2]), "=r"(r[3]) : "r"(addr));
}
__device__ __forceinline__ void mma_bf16(float* d, const uint32_t* a, uint32_t b0, uint32_t b1) {
    asm volatile("mma.sync.aligned.m16n8k16.row.col.f32.bf16.bf16.f32 "
                 "{%0,%1,%2,%3}, {%4,%5,%6,%7}, {%8,%9}, {%0,%1,%2,%3};"
                 : "+f"(d[0]), "+f"(d[1]), "+f"(d[2]), "+f"(d[3])
                 : "r"(a[0]), "r"(a[1]), "r"(a[2]), "r"(a[3]), "r"(b0), "r"(b1));
}
// pack two floats to bf16x2 (rn); low = a, high = b
__device__ __forceinline__ uint32_t cvt_bf16x2(float a, float b) {
    uint32_t r;
    asm("cvt.rn.bf16x2.f32 %0, %1, %2;" : "=r"(r) : "f"(b), "f"(a));
    return r;
}

// ---------------- xnorm (+ label decode in block 0, branchless detect) -----
__global__ void k_xnorm(const float* __restrict__ x, const int* __restrict__ raw) {
    __shared__ float wpz[16];
    __shared__ int is64;
    int b = blockIdx.x, t = threadIdx.x;
    if (b == 0 && t == 0) {
        int acc = 0;
        #pragma unroll
        for (int i = 0; i < 64; i++) acc |= raw[2 * i + 1];
        is64 = (acc == 0);
    }
    float v = x[b * D_ + t];
    float s = v * v;
    #pragma unroll
    for (int o = 16; o > 0; o >>= 1) s += __shfl_down_sync(0xffffffffu, s, o);
    if ((t & 31) == 0) wpz[t >> 5] = s;
    __syncthreads();
    if (b == 0 && t < 128) g_label[t] = is64 ? raw[2 * t] : raw[t];
    int h = t >> 6, k = t & 63;
    float ss = wpz[2 * h] + wpz[2 * h + 1];
    float xn = v * (1.0f / fmaxf(sqrtf(ss), 1e-12f));
    __nv_bfloat16 hi = __float2bfloat16(xn);
    __nv_bfloat16 lo = __float2bfloat16(xn - __bfloat162float(hi));
    unsigned by = (unsigned)b * 128u + 2u * (unsigned)k;
    unsigned sw = swz(by);
    g_Asw[h * 16384 + (sw >> 1)] = hi;
    g_Asw[h * 16384 + 8192 + (sw >> 1)] = lo;
}

// ---------------- pass1: GEMM + margin + quantize + partial sums ----------------
// (R9 champion configuration: acc[32], 3 CTAs/SM)
__global__ __launch_bounds__(256, 3) void k_pass1(const float* __restrict__ w) {
    extern __shared__ char sm[];
    const int tid = threadIdx.x, warp = tid >> 5, lane = tid & 31;
    const int h = blockIdx.y, tile = blockIdx.x, c0 = tile * TILE_C;
    uint32_t sb = smem_u32(sm);

    // copy A limbs (32KB, pre-swizzled; L2-resident)
    {
        const uint4* src = (const uint4*)(g_Asw + h * 16384);
        uint4* dst = (uint4*)(sm + OFF_AH);
        #pragma unroll
        for (int i = 0; i < 8; i++) dst[tid + 256 * i] = src[tid + 256 * i];
    }
    // convert B tile (64 cols) to bf16 limbs via packed cvt (+ per-col sqnorm)
    {
        int c = tid & 63, kg = tid >> 6;
        int cg = c0 + c;
        bool valid = cg < C_;
        const float* wp0 = w + ((size_t)(h * DK + kg * 16)) * C_ + cg;
        float ss = 0.f;
        #pragma unroll
        for (int i = 0; i < 8; i++) {
            float v0 = valid ? __ldg(wp0 + (size_t)(2 * i) * C_) : 0.f;
            float v1 = valid ? __ldg(wp0 + (size_t)(2 * i + 1) * C_) : 0.f;
            ss = fmaf(v0, v0, ss); ss = fmaf(v1, v1, ss);
            uint32_t hpk = cvt_bf16x2(v0, v1);
            float r0 = v0 - __uint_as_float(hpk << 16);
            float r1 = v1 - __uint_as_float(hpk & 0xFFFF0000u);
            uint32_t lpk = cvt_bf16x2(r0, r1);
            unsigned by = (unsigned)c * 128u + (unsigned)(kg * 32 + 4 * i);
            unsigned sw = swz(by);
            *(uint32_t*)(sm + OFF_BH + sw) = hpk;
            *(uint32_t*)(sm + OFF_BL + sw) = lpk;
        }
        ((float*)(sm + OFF_WP))[c * 4 + kg] = ss;
    }
    __syncthreads();
    if (tid < 64) {
        float* wp = (float*)(sm + OFF_WP);
        ((float*)(sm + OFF_WINV))[tid] =
            1.0f / fmaxf(sqrtf(wp[tid * 4] + wp[tid * 4 + 1] + wp[tid * 4 + 2] + wp[tid * 4 + 3]),
                         1e-12f);
    }

    const int wm = warp >> 1, wn = warp & 1;
    const int m0 = wm * 32, n0 = wn * 32;
    const int lrow = lane & 7, lt = lane >> 3;
    const int rowAo = lrow + (lt & 1) * 8;
    const int kbAo = (lt >> 1) * 16;
    const int rowBo = lrow + (lt >> 1) * 8;
    const int kbBo = (lt & 1) * 16;

    float acc[32];
    #pragma unroll
    for (int i = 0; i < 32; i++) acc[i] = 0.f;

    #pragma unroll
    for (int ks = 0; ks < 4; ks++) {
        uint32_t aH[2][4], aL[2][4];
        #pragma unroll
        for (int mb = 0; mb < 2; mb++) {
            unsigned sw = swz((unsigned)((m0 + mb * 16 + rowAo) * 128 + ks * 32 + kbAo));
            ldsm4(aH[mb], sb + OFF_AH + sw);
            ldsm4(aL[mb], sb + OFF_AL + sw);
        }
        #pragma unroll
        for (int p = 0; p < 2; p++) {
            unsigned sw = swz((unsigned)((n0 + p * 16 + rowBo) * 128 + ks * 32 + kbBo));
            uint32_t bH[4], bL[4];
            ldsm4(bH, sb + OFF_BH + sw);
            ldsm4(bL, sb + OFF_BL + sw);
            #pragma unroll
            for (int mb = 0; mb < 2; mb++) {
                float* d0 = acc + (mb * 4 + p * 2) * 4;
                float* d1 = acc + (mb * 4 + p * 2 + 1) * 4;
                mma_bf16(d0, aH[mb], bH[0], bH[1]);
                mma_bf16(d1, aH[mb], bH[2], bH[3]);
                mma_bf16(d0, aH[mb], bL[0], bL[1]);
                mma_bf16(d1, aH[mb], bL[2], bL[3]);
                mma_bf16(d0, aL[mb], bH[0], bH[1]);
                mma_bf16(d1, aL[mb], bH[2], bH[3]);
            }
        }
    }
    __syncthreads();

    // epilogue: cosine -> margin -> quantize int16 -> exp2 (for sums)
    const float* winv = (const float*)(sm + OFF_WINV);
    float* ps = (float*)(sm + OFF_PS);
    const int r0 = m0 + (lane >> 2);
    int labr[4];
    #pragma unroll
    for (int i = 0; i < 4; i++) labr[i] = g_label[r0 + (i >> 1) * 16 + (i & 1) * 8];

    float rsum[4] = {0.f, 0.f, 0.f, 0.f};
    const size_t wbase = (((size_t)h * NTILE + tile) * 8 + warp) * 512;

    #pragma unroll
    for (int mb = 0; mb < 2; mb++) {
        #pragma unroll
        for (int pn = 0; pn < 4; pn++) {
            int cb = n0 + pn * 8 + (lane & 3) * 2;
            float w0 = winv[cb], w1 = winv[cb + 1];
            int cg = c0 + cb;
            uint2 pk2;
            #pragma unroll
            for (int pr = 0; pr < 2; pr++) {
                int row = r0 + mb * 16 + pr * 8;
                int lb = labr[mb * 2 + pr];
                float v0 = acc[(mb * 4 + pn) * 4 + pr * 2 + 0];
                float v1 = acc[(mb * 4 + pn) * 4 + pr * 2 + 1];
                float cos0 = v0 * w0, cos1 = v1 * w1;
                int qi0 = 0, qi1 = 0;
                if (cg < C_) {
                    float val = cos0;
                    if (cg == lb) {
                        float sn = sqrtf(fmaxf(1.f - cos0 * cos0, 0.f));
                        float ph = cos0 * COS_M - sn * SIN_M;
                        val = (cos0 > TH_) ? ph : (cos0 - MM_);
                        g_coslab[row * H_ + h] = cos0;
                    }
                    qi0 = __float2int_rn(val * QS);
                    rsum[mb * 2 + pr] += ex2a(fmaf((float)qi0, QINV2, -S2_));
                }
                if (cg + 1 < C_) {
                    float val = cos1;
                    if (cg + 1 == lb) {
                        float sn = sqrtf(fmaxf(1.f - cos1 * cos1, 0.f));
                        float ph = cos1 * COS_M - sn * SIN_M;
                        val = (cos1 > TH_) ? ph : (cos1 - MM_);
                        g_coslab[row * H_ + h] = cos1;
                    }
                    qi1 = __float2int_rn(val * QS);
                    rsum[mb * 2 + pr] += ex2a(fmaf((float)qi1, QINV2, -S2_));
                }
                uint32_t pk = ((uint32_t)(uint16_t)(short)qi0) |
                              (((uint32_t)(uint16_t)(short)qi1) << 16);
                if (pr == 0) pk2.x = pk; else pk2.y = pk;
            }
            *(uint2*)&g_Q[wbase + (size_t)(mb * 4 + pn) * 64 + lane * 2] = pk2;
        }
    }
    #pragma unroll
    for (int i = 0; i < 4; i++) {
        float v = rsum[i];
        v += __shfl_down_sync(0xffffffffu, v, 1);
        v += __shfl_down_sync(0xffffffffu, v, 2);
        if ((lane & 3) == 0)
            ps[(r0 + (i >> 1) * 16 + (i & 1) * 8) * 2 + wn] = v;
    }
    __syncthreads();
    if (tid < 128)
        g_psum[((size_t)h * NTILE_PAD + tile) * B_ + tid] = ps[tid * 2] + ps[tid * 2 + 1];
}

// ---------------- fused reduction: stage-1 + last-block invsum --------------
__global__ void k_sumred() {
    __shared__ unsigned int ticket;
    int h = blockIdx.x, ch = blockIdx.y, b = threadIdx.x;
    int t0 = ch * CHTILES;
    float s = 0.f;
    #pragma unroll
    for (int t = 0; t < CHTILES; t++)
        s += g_psum[((size_t)h * NTILE_PAD + t0 + t) * B_ + b];
    g_psum2[(b * H_ + h) * NCHUNK + ch] = s;
    __threadfence();
    __syncthreads();
    if (threadIdx.x == 0) ticket = atomicAdd(&g_ctr, 1u);
    __syncthreads();
    if (ticket == H_ * NCHUNK - 1) {
        __threadfence();
        #pragma unroll
        for (int i = 0; i < 8; i++) {
            int idx = threadIdx.x + 128 * i;     // b*8+h
            const float4* p = (const float4*)&g_psum2[idx * NCHUNK];
            float ss = 0.f;
            #pragma unroll
            for (int cc = 0; cc < NCHUNK / 4; cc++) {
                float4 v = p[cc];
                ss += (v.x + v.y) + (v.z + v.w);
            }
            g_invsum[idx] = 1.0f / ss;
        }
        if (threadIdx.x == 0) g_ctr = 0;         // reset for next graph replay
    }
}

// ---------------- k_out: head-mean of softmax, mb-split for occupancy -------
// grid (NTILE, 2): blockIdx.y = mb half. Each warp reads its writer-warp's
// mb-half fragments: acc[16], 4 uint2 loads per head. Direct float2 stores.
__global__ __launch_bounds__(256, 5) void k_out(float* __restrict__ out, int write_loss) {
    __shared__ float invs[1024];
    __shared__ float red[256];
    const int tid = threadIdx.x, warp = tid >> 5, lane = tid & 31;
    const int tile = blockIdx.x, mb = blockIdx.y, c0 = tile * TILE_C;
    #pragma unroll
    for (int i = 0; i < 4; i++) invs[tid + 256 * i] = g_invsum[tid + 256 * i] * 0.125f;

    // block (0,0) additionally computes the NLL loss
    if (blockIdx.x == 0 && mb == 0) {
        float nll = 0.f;
        #pragma unroll
        for (int i = 0; i < 4; i++) {
            int idx = tid + 256 * i;              // b*8+h
            float iv = g_invsum[idx];
            float cos = g_coslab[idx];
            float sn = sqrtf(fmaxf(1.0f - cos * cos, 0.0f));
            float ph = cos * COS_M - sn * SIN_M;
            float val = (cos > TH_) ? ph : (cos - MM_);
            nll += -(S_ * val - S_ + logf(iv));
        }
        red[tid] = nll;
        __syncthreads();
        #pragma unroll
        for (int st = 128; st > 0; st >>= 1) {
            if (tid < st) red[tid] += red[tid + st];
            __syncthreads();
        }
        if (tid == 0 && write_loss)
            out[(size_t)B_ * C_] = red[0] * (1.0f / (B_ * H_));
    }
    __syncthreads();

    const int wm = warp >> 1, wn = warp & 1;
    const int r0 = wm * 32 + mb * 16 + (lane >> 2);   // rows r0, r0+8
    const int n0 = wn * 32;

    float acc[16];
    #pragma unroll
    for (int i = 0; i < 16; i++) acc[i] = 0.f;

    for (int h = 0; h < H_; h++) {
        const uint32_t* Qp = g_Q + (((size_t)h * NTILE + tile) * 8 + warp) * 512;
        float s0 = invs[r0 * H_ + h];
        float s1 = invs[(r0 + 8) * H_ + h];
        #pragma unroll
        for (int pn = 0; pn < 4; pn++) {
            uint2 pk2 = *(const uint2*)&Qp[(size_t)(mb * 4 + pn) * 64 + lane * 2];
            #pragma unroll
            for (int pr = 0; pr < 2; pr++) {
                uint32_t pk = pr ? pk2.y : pk2.x;
                float q0 = (float)(short)(pk & 0xFFFFu);
                float q1 = (float)(short)(pk >> 16);
                float sv = pr ? s1 : s0;
                float e0 = ex2a(fmaf(q0, QINV2, -S2_));
                float e1 = ex2a(fmaf(q1, QINV2, -S2_));
                int ai = pn * 4 + pr * 2;
                acc[ai]     = fmaf(e0, sv, acc[ai]);
                acc[ai + 1] = fmaf(e1, sv, acc[ai + 1]);
            }
        }
    }
    // direct stores: each quad covers a contiguous 32B sector per row
    #pragma unroll
    for (int pn = 0; pn < 4; pn++)
        #pragma unroll
        for (int pr = 0; pr < 2; pr++) {
            int row = r0 + pr * 8;
            int cg = c0 + n0 + pn * 8 + (lane & 3) * 2;
            int ai = pn * 4 + pr * 2;
            if (cg + 1 < C_) {
                *(float2*)&out[(size_t)row * C_ + cg] = make_float2(acc[ai], acc[ai + 1]);
            } else if (cg < C_) {
                out[(size_t)row * C_ + cg] = acc[ai];
            }
        }
}

// ---------------- launcher ----------------
extern "C" void kernel_launch(void* const* d_in, const int* in_sizes, int n_in,
                              void* d_out, int out_size) {
    const float* x = (const float*)d_in[0];
    const float* w = (const float*)d_in[1];
    const int*   lab = (const int*)d_in[2];
    float* out = (float*)d_out;
    (void)in_sizes; (void)n_in;

    static int inited = 0;
    if (!inited) {
        cudaFuncSetAttribute(k_pass1, cudaFuncAttributeMaxDynamicSharedMemorySize, SMEM1);
        inited = 1;
    }
    int write_loss = (out_size > B_ * C_) ? 1 : 0;

    k_xnorm<<<B_, D_>>>(x, lab);
    {
        dim3 g1(NTILE, H_);
        k_pass1<<<g1, 256, SMEM1>>>(w);
    }
    {
        dim3 g2(H_, NCHUNK);
        k_sumred<<<g2, B_>>>();
    }
    {
        dim3 g3(NTILE, 2);
        k_out<<<g3, 256>>>(out, write_loss);
    }
}

// round 12
// speedup vs baseline: 1.1149x; 1.0250x over previous
#include <cuda_runtime.h>
#include <cuda_bf16.h>
#include <math.h>
#include <stdint.h>
#include <stddef.h>

#define B_ 128
#define H_ 8
#define DK 64
#define C_ 50000
#define D_ 512
#define TILE_C 64
#define NTILE 782          // 782*64 = 50048 >= 50000
#define NTILE_PAD 800      // padded; tiles 782..799 never written (stay zero)
#define NCHUNK 8
#define CHTILES 100        // 8*100 = 800 == NTILE_PAD

#define COS_M 0.9800665778412416f
#define SIN_M 0.19866933079506122f
#define TH_  (-0.9800665778412416f)
#define MM_  0.039733866159012244f
#define S_   30.0f
#define QS   31500.0f
// exp(q*30/31500 - 30) == exp2(q*QINV2 - S2_)
#define QINV2 1.3739952770371081e-3f
#define S2_   43.280851226668902f
// with the 1/8 head-mean folded in: exp(...)*0.125 == exp2(q*QINV2 - (S2_+3))
#define S2K_  46.280851226668902f

// ---- pass1 smem layout (bytes) ----
#define OFF_AH 0
#define OFF_AL 16384
#define OFF_BH 32768
#define OFF_BL 40960
#define OFF_WINV 49152     // 64 floats
#define OFF_WP   49408     // 256 floats
#define OFF_PS   50432     // 256 floats
#define SMEM1    51456

// ---------------- device scratch ----------------
__device__ __align__(16) __nv_bfloat16 g_Asw[H_ * 16384];   // per head: [hi][lo], swizzled
__device__ uint32_t g_Q[(size_t)H_ * NTILE * 8 * 512];      // packed int16 q-pairs (102MB)
__device__ float g_psum[H_ * NTILE_PAD * B_];               // zero-padded tiles
__device__ __align__(16) float g_psum2[B_ * H_ * NCHUNK];   // transposed: [(b*8+h)][chunk]
__device__ float g_coslab[B_ * H_];
__device__ int   g_label[B_];

// ---------------- helpers ----------------
__device__ __forceinline__ uint32_t smem_u32(const void* p) {
    uint32_t a;
    asm("{ .reg .u64 t; cvta.to.shared.u64 t, %1; cvt.u32.u64 %0, t; }" : "=r"(a) : "l"(p));
    return a;
}
__device__ __forceinline__ unsigned swz(unsigned by) { return by ^ ((by >> 3) & 0x70); }
__device__ __forceinline__ float ex2a(float x) {
    float y;
    asm("ex2.approx.f32 %0, %1;" : "=f"(y) : "f"(x));
    return y;
}
__device__ __forceinline__ void ldsm4(uint32_t* r, uint32_t addr) {
    asm volatile("ldmatrix.sync.aligned.m8n8.x4.shared.b16 {%0,%1,%2,%3}, [%4];"
                 : "=r"(r[0]), "=r"(r[1]), "=r"(r[2]), "=r"(r[3]) : "r"(addr));
}
__device__ __forceinline__ void mma_bf16(float* d, const uint32_t* a, uint32_t b0, uint32_t b1) {
    asm volatile("mma.sync.aligned.m16n8k16.row.col.f32.bf16.bf16.f32 "
                 "{%0,%1,%2,%3}, {%4,%5,%6,%7}, {%8,%9}, {%0,%1,%2,%3};"
                 : "+f"(d[0]), "+f"(d[1]), "+f"(d[2]), "+f"(d[3])
                 : "r"(a[0]), "r"(a[1]), "r"(a[2]), "r"(a[3]), "r"(b0), "r"(b1));
}
// pack two floats to bf16x2 (rn); low = a, high = b
__device__ __forceinline__ uint32_t cvt_bf16x2(float a, float b) {
    uint32_t r;
    asm("cvt.rn.bf16x2.f32 %0, %1, %2;" : "=r"(r) : "f"(b), "f"(a));
    return r;
}

// ---------------- xnorm (+ label decode in block 0, branchless detect) -----
__global__ void k_xnorm(const float* __restrict__ x, const int* __restrict__ raw) {
    __shared__ float wpz[16];
    __shared__ int is64;
    int b = blockIdx.x, t = threadIdx.x;
    if (b == 0 && t == 0) {
        int acc = 0;
        #pragma unroll
        for (int i = 0; i < 64; i++) acc |= raw[2 * i + 1];
        is64 = (acc == 0);
    }
    float v = x[b * D_ + t];
    float s = v * v;
    #pragma unroll
    for (int o = 16; o > 0; o >>= 1) s += __shfl_down_sync(0xffffffffu, s, o);
    if ((t & 31) == 0) wpz[t >> 5] = s;
    __syncthreads();
    if (b == 0 && t < 128) g_label[t] = is64 ? raw[2 * t] : raw[t];
    int h = t >> 6, k = t & 63;
    float ss = wpz[2 * h] + wpz[2 * h + 1];
    float xn = v * (1.0f / fmaxf(sqrtf(ss), 1e-12f));
    __nv_bfloat16 hi = __float2bfloat16(xn);
    __nv_bfloat16 lo = __float2bfloat16(xn - __bfloat162float(hi));
    unsigned by = (unsigned)b * 128u + 2u * (unsigned)k;
    unsigned sw = swz(by);
    g_Asw[h * 16384 + (sw >> 1)] = hi;
    g_Asw[h * 16384 + 8192 + (sw >> 1)] = lo;
}

// ---------------- pass1: GEMM + margin + quantize + partial sums ----------------
// (R9 champion configuration: acc[32], 3 CTAs/SM)
__global__ __launch_bounds__(256, 3) void k_pass1(const float* __restrict__ w) {
    extern __shared__ char sm[];
    const int tid = threadIdx.x, warp = tid >> 5, lane = tid & 31;
    const int h = blockIdx.y, tile = blockIdx.x, c0 = tile * TILE_C;
    uint32_t sb = smem_u32(sm);

    // copy A limbs (32KB, pre-swizzled; L2-resident)
    {
        const uint4* src = (const uint4*)(g_Asw + h * 16384);
        uint4* dst = (uint4*)(sm + OFF_AH);
        #pragma unroll
        for (int i = 0; i < 8; i++) dst[tid + 256 * i] = src[tid + 256 * i];
    }
    // convert B tile (64 cols) to bf16 limbs via packed cvt (+ per-col sqnorm)
    {
        int c = tid & 63, kg = tid >> 6;
        int cg = c0 + c;
        bool valid = cg < C_;
        const float* wp0 = w + ((size_t)(h * DK + kg * 16)) * C_ + cg;
        float ss = 0.f;
        #pragma unroll
        for (int i = 0; i < 8; i++) {
            float v0 = valid ? __ldg(wp0 + (size_t)(2 * i) * C_) : 0.f;
            float v1 = valid ? __ldg(wp0 + (size_t)(2 * i + 1) * C_) : 0.f;
            ss = fmaf(v0, v0, ss); ss = fmaf(v1, v1, ss);
            uint32_t hpk = cvt_bf16x2(v0, v1);
            float r0 = v0 - __uint_as_float(hpk << 16);
            float r1 = v1 - __uint_as_float(hpk & 0xFFFF0000u);
            uint32_t lpk = cvt_bf16x2(r0, r1);
            unsigned by = (unsigned)c * 128u + (unsigned)(kg * 32 + 4 * i);
            unsigned sw = swz(by);
            *(uint32_t*)(sm + OFF_BH + sw) = hpk;
            *(uint32_t*)(sm + OFF_BL + sw) = lpk;
        }
        ((float*)(sm + OFF_WP))[c * 4 + kg] = ss;
    }
    __syncthreads();
    if (tid < 64) {
        float* wp = (float*)(sm + OFF_WP);
        ((float*)(sm + OFF_WINV))[tid] =
            1.0f / fmaxf(sqrtf(wp[tid * 4] + wp[tid * 4 + 1] + wp[tid * 4 + 2] + wp[tid * 4 + 3]),
                         1e-12f);
    }

    const int wm = warp >> 1, wn = warp & 1;
    const int m0 = wm * 32, n0 = wn * 32;
    const int lrow = lane & 7, lt = lane >> 3;
    const int rowAo = lrow + (lt & 1) * 8;
    const int kbAo = (lt >> 1) * 16;
    const int rowBo = lrow + (lt >> 1) * 8;
    const int kbBo = (lt & 1) * 16;

    float acc[32];
    #pragma unroll
    for (int i = 0; i < 32; i++) acc[i] = 0.f;

    #pragma unroll
    for (int ks = 0; ks < 4; ks++) {
        uint32_t aH[2][4], aL[2][4];
        #pragma unroll
        for (int mb = 0; mb < 2; mb++) {
            unsigned sw = swz((unsigned)((m0 + mb * 16 + rowAo) * 128 + ks * 32 + kbAo));
            ldsm4(aH[mb], sb + OFF_AH + sw);
            ldsm4(aL[mb], sb + OFF_AL + sw);
        }
        #pragma unroll
        for (int p = 0; p < 2; p++) {
            unsigned sw = swz((unsigned)((n0 + p * 16 + rowBo) * 128 + ks * 32 + kbBo));
            uint32_t bH[4], bL[4];
            ldsm4(bH, sb + OFF_BH + sw);
            ldsm4(bL, sb + OFF_BL + sw);
            #pragma unroll
            for (int mb = 0; mb < 2; mb++) {
                float* d0 = acc + (mb * 4 + p * 2) * 4;
                float* d1 = acc + (mb * 4 + p * 2 + 1) * 4;
                mma_bf16(d0, aH[mb], bH[0], bH[1]);
                mma_bf16(d1, aH[mb], bH[2], bH[3]);
                mma_bf16(d0, aH[mb], bL[0], bL[1]);
                mma_bf16(d1, aH[mb], bL[2], bL[3]);
                mma_bf16(d0, aL[mb], bH[0], bH[1]);
                mma_bf16(d1, aL[mb], bH[2], bH[3]);
            }
        }
    }
    __syncthreads();

    // epilogue: cosine -> margin -> quantize int16 -> exp2 (for sums)
    const float* winv = (const float*)(sm + OFF_WINV);
    float* ps = (float*)(sm + OFF_PS);
    const int r0 = m0 + (lane >> 2);
    int labr[4];
    #pragma unroll
    for (int i = 0; i < 4; i++) labr[i] = g_label[r0 + (i >> 1) * 16 + (i & 1) * 8];

    float rsum[4] = {0.f, 0.f, 0.f, 0.f};
    const size_t wbase = (((size_t)h * NTILE + tile) * 8 + warp) * 512;

    #pragma unroll
    for (int mb = 0; mb < 2; mb++) {
        #pragma unroll
        for (int pn = 0; pn < 4; pn++) {
            int cb = n0 + pn * 8 + (lane & 3) * 2;
            float w0 = winv[cb], w1 = winv[cb + 1];
            int cg = c0 + cb;
            uint2 pk2;
            #pragma unroll
            for (int pr = 0; pr < 2; pr++) {
                int row = r0 + mb * 16 + pr * 8;
                int lb = labr[mb * 2 + pr];
                float v0 = acc[(mb * 4 + pn) * 4 + pr * 2 + 0];
                float v1 = acc[(mb * 4 + pn) * 4 + pr * 2 + 1];
                float cos0 = v0 * w0, cos1 = v1 * w1;
                int qi0 = 0, qi1 = 0;
                if (cg < C_) {
                    float val = cos0;
                    if (cg == lb) {
                        float sn = sqrtf(fmaxf(1.f - cos0 * cos0, 0.f));
                        float ph = cos0 * COS_M - sn * SIN_M;
                        val = (cos0 > TH_) ? ph : (cos0 - MM_);
                        g_coslab[row * H_ + h] = cos0;
                    }
                    qi0 = __float2int_rn(val * QS);
                    rsum[mb * 2 + pr] += ex2a(fmaf((float)qi0, QINV2, -S2_));
                }
                if (cg + 1 < C_) {
                    float val = cos1;
                    if (cg + 1 == lb) {
                        float sn = sqrtf(fmaxf(1.f - cos1 * cos1, 0.f));
                        float ph = cos1 * COS_M - sn * SIN_M;
                        val = (cos1 > TH_) ? ph : (cos1 - MM_);
                        g_coslab[row * H_ + h] = cos1;
                    }
                    qi1 = __float2int_rn(val * QS);
                    rsum[mb * 2 + pr] += ex2a(fmaf((float)qi1, QINV2, -S2_));
                }
                uint32_t pk = ((uint32_t)(uint16_t)(short)qi0) |
                              (((uint32_t)(uint16_t)(short)qi1) << 16);
                if (pr == 0) pk2.x = pk; else pk2.y = pk;
            }
            *(uint2*)&g_Q[wbase + (size_t)(mb * 4 + pn) * 64 + lane * 2] = pk2;
        }
    }
    #pragma unroll
    for (int i = 0; i < 4; i++) {
        float v = rsum[i];
        v += __shfl_down_sync(0xffffffffu, v, 1);
        v += __shfl_down_sync(0xffffffffu, v, 2);
        if ((lane & 3) == 0)
            ps[(r0 + (i >> 1) * 16 + (i & 1) * 8) * 2 + wn] = v;
    }
    __syncthreads();
    if (tid < 128)
        g_psum[((size_t)h * NTILE_PAD + tile) * B_ + tid] = ps[tid * 2] + ps[tid * 2 + 1];
}

// ---------------- stage-1 reduction (8 chunks; transposed output) -----------
__global__ void k_sumexp1() {
    int h = blockIdx.x, ch = blockIdx.y, b = threadIdx.x;
    int t0 = ch * CHTILES;
    float s = 0.f;
    #pragma unroll
    for (int t = 0; t < CHTILES; t++)
        s += g_psum[((size_t)h * NTILE_PAD + t0 + t) * B_ + b];
    g_psum2[(b * H_ + h) * NCHUNK + ch] = s;
}

// ---------------- k_out: head-mean of softmax (inline invsum + loss) --------
// grid (NTILE, 2): blockIdx.y = mb half. acc[16] per warp, direct float2 stores.
__global__ __launch_bounds__(256, 5) void k_out(float* __restrict__ out, int write_loss) {
    __shared__ float invs[1024];
    __shared__ float red[256];
    const int tid = threadIdx.x, warp = tid >> 5, lane = tid & 31;
    const int tile = blockIdx.x, mb = blockIdx.y, c0 = tile * TILE_C;

    // fold 8 chunk partials -> inv per (b,h); g_psum2 is 32KB, L2-hot
    #pragma unroll
    for (int i = 0; i < 4; i++) {
        int idx = tid + 256 * i;
        const float4* p = (const float4*)&g_psum2[idx * NCHUNK];
        float4 a = p[0], b4 = p[1];
        float ssum = ((a.x + a.y) + (a.z + a.w)) + ((b4.x + b4.y) + (b4.z + b4.w));
        invs[idx] = 1.0f / ssum;
    }
    __syncthreads();

    // block (0,0) additionally computes the NLL loss
    if (blockIdx.x == 0 && mb == 0) {
        float nll = 0.f;
        #pragma unroll
        for (int i = 0; i < 4; i++) {
            int idx = tid + 256 * i;              // b*8+h
            float iv = invs[idx];
            float cos = g_coslab[idx];
            float sn = sqrtf(fmaxf(1.0f - cos * cos, 0.0f));
            float ph = cos * COS_M - sn * SIN_M;
            float val = (cos > TH_) ? ph : (cos - MM_);
            nll += -(S_ * val - S_ + logf(iv));
        }
        red[tid] = nll;
        __syncthreads();
        #pragma unroll
        for (int st = 128; st > 0; st >>= 1) {
            if (tid < st) red[tid] += red[tid + st];
            __syncthreads();
        }
        if (tid == 0 && write_loss)
            out[(size_t)B_ * C_] = red[0] * (1.0f / (B_ * H_));
    }

    const int wm = warp >> 1, wn = warp & 1;
    const int r0 = wm * 32 + mb * 16 + (lane >> 2);   // rows r0, r0+8
    const int n0 = wn * 32;

    float acc[16];
    #pragma unroll
    for (int i = 0; i < 16; i++) acc[i] = 0.f;

    for (int h = 0; h < H_; h++) {
        const uint32_t* Qp = g_Q + (((size_t)h * NTILE + tile) * 8 + warp) * 512;
        float s0 = invs[r0 * H_ + h];
        float s1 = invs[(r0 + 8) * H_ + h];
        #pragma unroll
        for (int pn = 0; pn < 4; pn++) {
            uint2 pk2 = *(const uint2*)&Qp[(size_t)(mb * 4 + pn) * 64 + lane * 2];
            #pragma unroll
            for (int pr = 0; pr < 2; pr++) {
                uint32_t pk = pr ? pk2.y : pk2.x;
                float q0 = (float)(short)(pk & 0xFFFFu);
                float q1 = (float)(short)(pk >> 16);
                float sv = pr ? s1 : s0;
                // S2K_ folds the 1/8 head-mean into the exponent
                float e0 = ex2a(fmaf(q0, QINV2, -S2K_));
                float e1 = ex2a(fmaf(q1, QINV2, -S2K_));
                int ai = pn * 4 + pr * 2;
                acc[ai]     = fmaf(e0, sv, acc[ai]);
                acc[ai + 1] = fmaf(e1, sv, acc[ai + 1]);
            }
        }
    }
    // direct stores: each quad covers a contiguous 32B sector per row
    #pragma unroll
    for (int pn = 0; pn < 4; pn++)
        #pragma unroll
        for (int pr = 0; pr < 2; pr++) {
            int row = r0 + pr * 8;
            int cg = c0 + n0 + pn * 8 + (lane & 3) * 2;
            int ai = pn * 4 + pr * 2;
            if (cg + 1 < C_) {
                *(float2*)&out[(size_t)row * C_ + cg] = make_float2(acc[ai], acc[ai + 1]);
            } else if (cg < C_) {
                out[(size_t)row * C_ + cg] = acc[ai];
            }
        }
}

// ---------------- launcher ----------------
extern "C" void kernel_launch(void* const* d_in, const int* in_sizes, int n_in,
                              void* d_out, int out_size) {
    const float* x = (const float*)d_in[0];
    const float* w = (const float*)d_in[1];
    const int*   lab = (const int*)d_in[2];
    float* out = (float*)d_out;
    (void)in_sizes; (void)n_in;

    static int inited = 0;
    if (!inited) {
        cudaFuncSetAttribute(k_pass1, cudaFuncAttributeMaxDynamicSharedMemorySize, SMEM1);
        inited = 1;
    }
    int write_loss = (out_size > B_ * C_) ? 1 : 0;

    k_xnorm<<<B_, D_>>>(x, lab);
    {
        dim3 g1(NTILE, H_);
        k_pass1<<<g1, 256, SMEM1>>>(w);
    }
    {
        dim3 g2(H_, NCHUNK);
        k_sumexp1<<<g2, B_>>>();
    }
    {
        dim3 g3(NTILE, 2);
        k_out<<<g3, 256>>>(out, write_loss);
    }
}